// round 1
// baseline (speedup 1.0000x reference)
#include <cuda_runtime.h>

#define D  64
#define RK 16
#define MAXN 100000

// Scratch (allocation-free rule: __device__ globals)
static __device__ float g_Asrc[(size_t)MAXN * D];  // sg gate per node
static __device__ float g_Adst[(size_t)MAXN * D];  // dg gate per node
static __device__ float g_Abh [(size_t)MAXN * D];  // du gate per node (Bh)
static __device__ float g_Sh  [(size_t)MAXN * D];  // segment_sum(Bh[src]*sigma, dst)
static __device__ float g_Ss  [(size_t)MAXN * D];  // segment_sum(sigma, dst)

__device__ __forceinline__ float sigm(float x) {
    return __fdividef(1.0f, 1.0f + __expf(-x));
}

// ---------------------------------------------------------------- zero scratch
__global__ void k_zero(int n4) {
    int i = blockIdx.x * blockDim.x + threadIdx.x;
    int stride = gridDim.x * blockDim.x;
    float4 z = make_float4(0.f, 0.f, 0.f, 0.f);
    float4* a = (float4*)g_Sh;
    float4* b = (float4*)g_Ss;
    for (int j = i; j < n4; j += stride) { a[j] = z; b[j] = z; }
}

// ------------------------------------------------- node precompute (3 gates)
// thread-per-node; weights broadcast from shared; rank-16 accumulators in regs
__global__ void __launch_bounds__(256) k_nodepre(
    const float* __restrict__ nf, int N,
    const float* __restrict__ w1a, const float* __restrict__ w2a, const float* __restrict__ ba,
    const float* __restrict__ w1b, const float* __restrict__ w2b, const float* __restrict__ bb,
    const float* __restrict__ w1c, const float* __restrict__ w2c, const float* __restrict__ bc)
{
    __shared__ float s_w1[3][D * RK];
    __shared__ float s_w2[3][RK * D];
    __shared__ float s_b[3][D];
    for (int i = threadIdx.x; i < D * RK; i += blockDim.x) {
        s_w1[0][i] = w1a[i]; s_w1[1][i] = w1b[i]; s_w1[2][i] = w1c[i];
        s_w2[0][i] = w2a[i]; s_w2[1][i] = w2b[i]; s_w2[2][i] = w2c[i];
    }
    for (int i = threadIdx.x; i < D; i += blockDim.x) {
        s_b[0][i] = ba[i]; s_b[1][i] = bb[i]; s_b[2][i] = bc[i];
    }
    __syncthreads();

    int n = blockIdx.x * blockDim.x + threadIdx.x;
    if (n >= N) return;

    const float4* x4 = (const float4*)(nf + (size_t)n * D);
    float t0[RK], t1[RK], t2[RK];
#pragma unroll
    for (int r = 0; r < RK; r++) { t0[r] = 0.f; t1[r] = 0.f; t2[r] = 0.f; }

    for (int k4 = 0; k4 < D / 4; k4++) {
        float4 xq = x4[k4];
#pragma unroll
        for (int j = 0; j < 4; j++) {
            float xk = (j == 0) ? xq.x : (j == 1) ? xq.y : (j == 2) ? xq.z : xq.w;
            int k = 4 * k4 + j;
            const float4* p0 = (const float4*)&s_w1[0][k * RK];
            const float4* p1 = (const float4*)&s_w1[1][k * RK];
            const float4* p2 = (const float4*)&s_w1[2][k * RK];
#pragma unroll
            for (int r4 = 0; r4 < RK / 4; r4++) {
                float4 w;
                w = p0[r4];
                t0[4*r4+0] += xk*w.x; t0[4*r4+1] += xk*w.y; t0[4*r4+2] += xk*w.z; t0[4*r4+3] += xk*w.w;
                w = p1[r4];
                t1[4*r4+0] += xk*w.x; t1[4*r4+1] += xk*w.y; t1[4*r4+2] += xk*w.z; t1[4*r4+3] += xk*w.w;
                w = p2[r4];
                t2[4*r4+0] += xk*w.x; t2[4*r4+1] += xk*w.y; t2[4*r4+2] += xk*w.z; t2[4*r4+3] += xk*w.w;
            }
        }
    }

    float4* o0 = (float4*)(g_Asrc + (size_t)n * D);
    float4* o1 = (float4*)(g_Adst + (size_t)n * D);
    float4* o2 = (float4*)(g_Abh  + (size_t)n * D);
    for (int d4 = 0; d4 < D / 4; d4++) {
        float4 a0 = ((const float4*)s_b[0])[d4];
        float4 a1 = ((const float4*)s_b[1])[d4];
        float4 a2 = ((const float4*)s_b[2])[d4];
#pragma unroll
        for (int r = 0; r < RK; r++) {
            float4 w;
            w = ((const float4*)s_w2[0])[r * (D/4) + d4];
            a0.x += t0[r]*w.x; a0.y += t0[r]*w.y; a0.z += t0[r]*w.z; a0.w += t0[r]*w.w;
            w = ((const float4*)s_w2[1])[r * (D/4) + d4];
            a1.x += t1[r]*w.x; a1.y += t1[r]*w.y; a1.z += t1[r]*w.z; a1.w += t1[r]*w.w;
            w = ((const float4*)s_w2[2])[r * (D/4) + d4];
            a2.x += t2[r]*w.x; a2.y += t2[r]*w.y; a2.z += t2[r]*w.z; a2.w += t2[r]*w.w;
        }
        o0[d4] = a0; o1[d4] = a1; o2[d4] = a2;
    }
}

// ------------------------------------------------------------------ edge pass
// thread-per-edge: edge gate lowrank, gathers, sigmoid, atomic scatter,
// LayerNorm (m staged in shared [d][tid]), SiLU, residual, write y.
__global__ void __launch_bounds__(128) k_edge(
    const float* __restrict__ ef, const int* __restrict__ src, const int* __restrict__ dst,
    const float* __restrict__ w1, const float* __restrict__ w2, const float* __restrict__ bias,
    const float* __restrict__ lng, const float* __restrict__ lnb,
    float* __restrict__ yout, int E)
{
    __shared__ float s_w1[D * RK];
    __shared__ float s_w2[RK * D];
    __shared__ float s_b[D], s_g[D], s_lb[D];
    __shared__ float s_m[D][128];

    for (int i = threadIdx.x; i < D * RK; i += blockDim.x) { s_w1[i] = w1[i]; s_w2[i] = w2[i]; }
    for (int i = threadIdx.x; i < D; i += blockDim.x) { s_b[i] = bias[i]; s_g[i] = lng[i]; s_lb[i] = lnb[i]; }
    __syncthreads();

    int e = blockIdx.x * blockDim.x + threadIdx.x;
    if (e >= E) return;

    const float4* x4 = (const float4*)(ef + (size_t)e * D);

    // stage 1: t = xe @ w1   [R]
    float t[RK];
#pragma unroll
    for (int r = 0; r < RK; r++) t[r] = 0.f;
    for (int k4 = 0; k4 < D / 4; k4++) {
        float4 xq = x4[k4];
#pragma unroll
        for (int j = 0; j < 4; j++) {
            float xk = (j == 0) ? xq.x : (j == 1) ? xq.y : (j == 2) ? xq.z : xq.w;
            const float4* p = (const float4*)&s_w1[(4 * k4 + j) * RK];
#pragma unroll
            for (int r4 = 0; r4 < RK / 4; r4++) {
                float4 w = p[r4];
                t[4*r4+0] += xk*w.x; t[4*r4+1] += xk*w.y; t[4*r4+2] += xk*w.z; t[4*r4+3] += xk*w.w;
            }
        }
    }

    int s  = src[e];
    int dd = dst[e];
    const float4* As = (const float4*)(g_Asrc + (size_t)s  * D);
    const float4* Ad = (const float4*)(g_Adst + (size_t)dd * D);
    const float4* Ab = (const float4*)(g_Abh  + (size_t)s  * D);
    float* Shp = g_Sh + (size_t)dd * D;
    float* Ssp = g_Ss + (size_t)dd * D;

    float sum = 0.f, ssq = 0.f;
    int tid = threadIdx.x;

    // stage 2: m = t @ w2 + b + A_src[s] + A_dst[dd]; sigma; scatter; LN stats
    for (int d4 = 0; d4 < D / 4; d4++) {
        float4 acc = ((const float4*)s_b)[d4];
#pragma unroll
        for (int r = 0; r < RK; r++) {
            float4 w = ((const float4*)s_w2)[r * (D/4) + d4];
            acc.x += t[r]*w.x; acc.y += t[r]*w.y; acc.z += t[r]*w.z; acc.w += t[r]*w.w;
        }
        float4 a  = As[d4];
        float4 b2 = Ad[d4];
        acc.x += a.x + b2.x; acc.y += a.y + b2.y; acc.z += a.z + b2.z; acc.w += a.w + b2.w;

        int base = 4 * d4;
        s_m[base+0][tid] = acc.x; s_m[base+1][tid] = acc.y;
        s_m[base+2][tid] = acc.z; s_m[base+3][tid] = acc.w;

        sum += acc.x + acc.y + acc.z + acc.w;
        ssq += acc.x*acc.x + acc.y*acc.y + acc.z*acc.z + acc.w*acc.w;

        float4 sg;
        sg.x = sigm(acc.x); sg.y = sigm(acc.y); sg.z = sigm(acc.z); sg.w = sigm(acc.w);
        float4 bh = Ab[d4];

        atomicAdd(Ssp + base + 0, sg.x);
        atomicAdd(Ssp + base + 1, sg.y);
        atomicAdd(Ssp + base + 2, sg.z);
        atomicAdd(Ssp + base + 3, sg.w);
        atomicAdd(Shp + base + 0, bh.x * sg.x);
        atomicAdd(Shp + base + 1, bh.y * sg.y);
        atomicAdd(Shp + base + 2, bh.z * sg.z);
        atomicAdd(Shp + base + 3, bh.w * sg.w);
    }

    float mu   = sum * (1.0f / D);
    float var  = fmaf(-mu, mu, ssq * (1.0f / D));
    float rstd = rsqrtf(var + 1e-5f);

    float4* yo = (float4*)(yout + (size_t)e * D);
    for (int d4 = 0; d4 < D / 4; d4++) {
        int base = 4 * d4;
        float4 xe = x4[d4];
        float m0 = s_m[base+0][tid], m1 = s_m[base+1][tid];
        float m2 = s_m[base+2][tid], m3 = s_m[base+3][tid];
        float v0 = (m0 - mu) * rstd * s_g[base+0] + s_lb[base+0];
        float v1 = (m1 - mu) * rstd * s_g[base+1] + s_lb[base+1];
        float v2 = (m2 - mu) * rstd * s_g[base+2] + s_lb[base+2];
        float v3 = (m3 - mu) * rstd * s_g[base+3] + s_lb[base+3];
        float4 o;
        o.x = v0 * sigm(v0) + xe.x;
        o.y = v1 * sigm(v1) + xe.y;
        o.z = v2 * sigm(v2) + xe.z;
        o.w = v3 * sigm(v3) + xe.w;
        yo[d4] = o;
    }
}

// ------------------------------------------------------------- node update
__global__ void __launch_bounds__(128) k_nodeupd(
    const float* __restrict__ nf,
    const float* __restrict__ w1, const float* __restrict__ w2, const float* __restrict__ bias,
    const float* __restrict__ lng, const float* __restrict__ lnb,
    float* __restrict__ xout, int N)
{
    __shared__ float s_w1[D * RK];
    __shared__ float s_w2[RK * D];
    __shared__ float s_b[D], s_g[D], s_lb[D];
    __shared__ float s_m[D][128];

    for (int i = threadIdx.x; i < D * RK; i += blockDim.x) { s_w1[i] = w1[i]; s_w2[i] = w2[i]; }
    for (int i = threadIdx.x; i < D; i += blockDim.x) { s_b[i] = bias[i]; s_g[i] = lng[i]; s_lb[i] = lnb[i]; }
    __syncthreads();

    int n = blockIdx.x * blockDim.x + threadIdx.x;
    if (n >= N) return;

    const float4* x4 = (const float4*)(nf + (size_t)n * D);
    float t[RK];
#pragma unroll
    for (int r = 0; r < RK; r++) t[r] = 0.f;
    for (int k4 = 0; k4 < D / 4; k4++) {
        float4 xq = x4[k4];
#pragma unroll
        for (int j = 0; j < 4; j++) {
            float xk = (j == 0) ? xq.x : (j == 1) ? xq.y : (j == 2) ? xq.z : xq.w;
            const float4* p = (const float4*)&s_w1[(4 * k4 + j) * RK];
#pragma unroll
            for (int r4 = 0; r4 < RK / 4; r4++) {
                float4 w = p[r4];
                t[4*r4+0] += xk*w.x; t[4*r4+1] += xk*w.y; t[4*r4+2] += xk*w.z; t[4*r4+3] += xk*w.w;
            }
        }
    }

    const float4* Sh4 = (const float4*)(g_Sh + (size_t)n * D);
    const float4* Ss4 = (const float4*)(g_Ss + (size_t)n * D);

    float sum = 0.f, ssq = 0.f;
    int tid = threadIdx.x;

    for (int d4 = 0; d4 < D / 4; d4++) {
        float4 acc = ((const float4*)s_b)[d4];
#pragma unroll
        for (int r = 0; r < RK; r++) {
            float4 w = ((const float4*)s_w2)[r * (D/4) + d4];
            acc.x += t[r]*w.x; acc.y += t[r]*w.y; acc.z += t[r]*w.z; acc.w += t[r]*w.w;
        }
        float4 hn = Sh4[d4];
        float4 hd = Ss4[d4];
        acc.x += hn.x * __fdividef(1.f, hd.x + 1e-6f);
        acc.y += hn.y * __fdividef(1.f, hd.y + 1e-6f);
        acc.z += hn.z * __fdividef(1.f, hd.z + 1e-6f);
        acc.w += hn.w * __fdividef(1.f, hd.w + 1e-6f);

        int base = 4 * d4;
        s_m[base+0][tid] = acc.x; s_m[base+1][tid] = acc.y;
        s_m[base+2][tid] = acc.z; s_m[base+3][tid] = acc.w;
        sum += acc.x + acc.y + acc.z + acc.w;
        ssq += acc.x*acc.x + acc.y*acc.y + acc.z*acc.z + acc.w*acc.w;
    }

    float mu   = sum * (1.0f / D);
    float var  = fmaf(-mu, mu, ssq * (1.0f / D));
    float rstd = rsqrtf(var + 1e-5f);

    float4* xo = (float4*)(xout + (size_t)n * D);
    for (int d4 = 0; d4 < D / 4; d4++) {
        int base = 4 * d4;
        float4 xn = x4[d4];
        float m0 = s_m[base+0][tid], m1 = s_m[base+1][tid];
        float m2 = s_m[base+2][tid], m3 = s_m[base+3][tid];
        float v0 = (m0 - mu) * rstd * s_g[base+0] + s_lb[base+0];
        float v1 = (m1 - mu) * rstd * s_g[base+1] + s_lb[base+1];
        float v2 = (m2 - mu) * rstd * s_g[base+2] + s_lb[base+2];
        float v3 = (m3 - mu) * rstd * s_g[base+3] + s_lb[base+3];
        float4 o;
        o.x = v0 * sigm(v0) + xn.x;
        o.y = v1 * sigm(v1) + xn.y;
        o.z = v2 * sigm(v2) + xn.z;
        o.w = v3 * sigm(v3) + xn.w;
        xo[d4] = o;
    }
}

// ---------------------------------------------------------------------- launch
extern "C" void kernel_launch(void* const* d_in, const int* in_sizes, int n_in,
                              void* d_out, int out_size)
{
    const float* nf  = (const float*)d_in[0];
    const float* ef  = (const float*)d_in[1];
    const int*   src = (const int*)d_in[2];
    const int*   dst = (const int*)d_in[3];
    const float* sgw1 = (const float*)d_in[4];
    const float* sgw2 = (const float*)d_in[5];
    const float* sgb  = (const float*)d_in[6];
    const float* dgw1 = (const float*)d_in[7];
    const float* dgw2 = (const float*)d_in[8];
    const float* dgb  = (const float*)d_in[9];
    const float* egw1 = (const float*)d_in[10];
    const float* egw2 = (const float*)d_in[11];
    const float* egb  = (const float*)d_in[12];
    const float* suw1 = (const float*)d_in[13];
    const float* suw2 = (const float*)d_in[14];
    const float* sub  = (const float*)d_in[15];
    const float* duw1 = (const float*)d_in[16];
    const float* duw2 = (const float*)d_in[17];
    const float* dub  = (const float*)d_in[18];
    const float* ln_n_g = (const float*)d_in[19];
    const float* ln_n_b = (const float*)d_in[20];
    const float* ln_e_g = (const float*)d_in[21];
    const float* ln_e_b = (const float*)d_in[22];

    int N = in_sizes[0] / D;
    int E = in_sizes[2];

    float* xout = (float*)d_out;
    float* yout = xout + (size_t)N * D;

    k_zero<<<1024, 256>>>(N * D / 4);
    k_nodepre<<<(N + 255) / 256, 256>>>(nf, N,
                                        sgw1, sgw2, sgb,
                                        dgw1, dgw2, dgb,
                                        duw1, duw2, dub);
    k_edge<<<(E + 127) / 128, 128>>>(ef, src, dst,
                                     egw1, egw2, egb,
                                     ln_e_g, ln_e_b, yout, E);
    k_nodeupd<<<(N + 127) / 128, 128>>>(nf, suw1, suw2, sub,
                                        ln_n_g, ln_n_b, xout, N);
}

// round 2
// speedup vs baseline: 2.5268x; 2.5268x over previous
#include <cuda_runtime.h>

#define D    64
#define D4   16
#define RK   16
#define MAXN 100000

// Scratch (allocation-free rule: __device__ globals). float4 for 16B alignment.
static __device__ float4 g_Asrc[(size_t)MAXN * D4];  // sg gate per node
static __device__ float4 g_Adst[(size_t)MAXN * D4];  // dg gate per node
static __device__ float4 g_Abh [(size_t)MAXN * D4];  // du gate per node (Bh)
static __device__ float4 g_Sh  [(size_t)MAXN * D4];  // segsum(Bh[src]*sigma, dst)
static __device__ float4 g_Ss  [(size_t)MAXN * D4];  // segsum(sigma, dst)

__device__ __forceinline__ float sigm(float x) {
    return __fdividef(1.0f, 1.0f + __expf(-x));
}

// Vectorized fp32 reduction atomic (sm_90+): 1 instr per 16B, coalesced rows.
__device__ __forceinline__ void red_add_v4(float4* p, float4 v) {
    asm volatile("red.global.add.v4.f32 [%0], {%1,%2,%3,%4};"
                 :: "l"(p), "f"(v.x), "f"(v.y), "f"(v.z), "f"(v.w)
                 : "memory");
}

// ---------------------------------------------------------------- zero scratch
__global__ void k_zero(int n4) {
    int i = blockIdx.x * blockDim.x + threadIdx.x;
    int st = gridDim.x * blockDim.x;
    float4 z = make_float4(0.f, 0.f, 0.f, 0.f);
    for (int j = i; j < n4; j += st) { g_Sh[j] = z; g_Ss[j] = z; }
}

// ------------------------------------------------- node precompute (3 gates)
// 16 lanes per node row; block = 256 threads = 16 nodes. All coalesced.
__global__ void __launch_bounds__(256) k_nodepre(
    const float* __restrict__ nf, int N,
    const float* __restrict__ w1a, const float* __restrict__ w2a, const float* __restrict__ ba,
    const float* __restrict__ w1b, const float* __restrict__ w2b, const float* __restrict__ bb,
    const float* __restrict__ w1c, const float* __restrict__ w2c, const float* __restrict__ bc)
{
    __shared__ float  s_w1[3][D * RK];     // [gate][k*RK+r]
    __shared__ float4 s_w2[3][RK * D4];    // [gate][r*D4+d4]
    __shared__ float4 s_b[3][D4];
    __shared__ float4 s_x[16][D4];
    __shared__ float  s_t[3][16][RK];

    int tid = threadIdx.x;
    for (int i = tid; i < D * RK; i += 256) {
        s_w1[0][i] = w1a[i]; s_w1[1][i] = w1b[i]; s_w1[2][i] = w1c[i];
        ((float*)s_w2[0])[i] = w2a[i];
        ((float*)s_w2[1])[i] = w2b[i];
        ((float*)s_w2[2])[i] = w2c[i];
    }
    if (tid < D) {
        ((float*)s_b[0])[tid] = ba[tid];
        ((float*)s_b[1])[tid] = bb[tid];
        ((float*)s_b[2])[tid] = bc[tid];
    }
    {   // coalesced row load: thread i loads float4 #(block*256+i)
        int idx = blockIdx.x * 256 + tid;
        if (idx < N * D4) s_x[tid >> 4][tid & 15] = ((const float4*)nf)[idx];
    }
    __syncthreads();

    int row = tid >> 4, lane = tid & 15;
    int n = blockIdx.x * 16 + row;

    const float* xr = (const float*)s_x[row];
    float t0 = 0.f, t1 = 0.f, t2 = 0.f;
#pragma unroll
    for (int k = 0; k < D; k++) {
        float xk = xr[k];
        t0 = fmaf(xk, s_w1[0][k * RK + lane], t0);
        t1 = fmaf(xk, s_w1[1][k * RK + lane], t1);
        t2 = fmaf(xk, s_w1[2][k * RK + lane], t2);
    }
    s_t[0][row][lane] = t0; s_t[1][row][lane] = t1; s_t[2][row][lane] = t2;
    __syncthreads();

    if (n >= N) return;

    float4 a0 = s_b[0][lane], a1 = s_b[1][lane], a2 = s_b[2][lane];
#pragma unroll
    for (int r = 0; r < RK; r++) {
        float u0 = s_t[0][row][r], u1 = s_t[1][row][r], u2 = s_t[2][row][r];
        float4 w0 = s_w2[0][r * D4 + lane];
        float4 w1_ = s_w2[1][r * D4 + lane];
        float4 w2_ = s_w2[2][r * D4 + lane];
        a0.x = fmaf(u0, w0.x, a0.x); a0.y = fmaf(u0, w0.y, a0.y);
        a0.z = fmaf(u0, w0.z, a0.z); a0.w = fmaf(u0, w0.w, a0.w);
        a1.x = fmaf(u1, w1_.x, a1.x); a1.y = fmaf(u1, w1_.y, a1.y);
        a1.z = fmaf(u1, w1_.z, a1.z); a1.w = fmaf(u1, w1_.w, a1.w);
        a2.x = fmaf(u2, w2_.x, a2.x); a2.y = fmaf(u2, w2_.y, a2.y);
        a2.z = fmaf(u2, w2_.z, a2.z); a2.w = fmaf(u2, w2_.w, a2.w);
    }
    size_t o = (size_t)n * D4 + lane;
    g_Asrc[o] = a0; g_Adst[o] = a1; g_Abh[o] = a2;
}

// ------------------------------------------------------------------ edge pass
// 16 lanes per edge: lowrank gate, coalesced gathers, vector red scatter,
// shuffle LayerNorm, SiLU, residual, coalesced y write.
__global__ void __launch_bounds__(256) k_edge(
    const float* __restrict__ ef, const int* __restrict__ src, const int* __restrict__ dst,
    const float* __restrict__ w1, const float* __restrict__ w2, const float* __restrict__ bias,
    const float* __restrict__ lng, const float* __restrict__ lnb,
    float* __restrict__ yout, int E)
{
    __shared__ float  s_w1[D * RK];
    __shared__ float4 s_w2[RK * D4];
    __shared__ float4 s_b[D4], s_g[D4], s_lb[D4];
    __shared__ float4 s_x[16][D4];
    __shared__ float  s_t[16][RK];
    __shared__ int    s_src[16], s_dst[16];

    int tid = threadIdx.x;
    for (int i = tid; i < D * RK; i += 256) {
        s_w1[i] = w1[i];
        ((float*)s_w2)[i] = w2[i];
    }
    if (tid < D) {
        ((float*)s_b)[tid] = bias[tid];
        ((float*)s_g)[tid] = lng[tid];
        ((float*)s_lb)[tid] = lnb[tid];
    }
    int e0 = blockIdx.x * 16;
    if (tid < 16) {
        int ec = min(e0 + tid, E - 1);
        s_src[tid] = src[ec];
        s_dst[tid] = dst[ec];
    }
    {
        int idx = blockIdx.x * 256 + tid;
        if (idx < E * D4) s_x[tid >> 4][tid & 15] = ((const float4*)ef)[idx];
    }
    __syncthreads();

    int row = tid >> 4, lane = tid & 15;
    int e = e0 + row;
    bool valid = (e < E);

    // stage 1: each thread computes one t[r] for its edge
    const float* xr = (const float*)s_x[row];
    float t = 0.f;
#pragma unroll
    for (int k = 0; k < D; k++) t = fmaf(xr[k], s_w1[k * RK + lane], t);
    s_t[row][lane] = t;
    __syncthreads();

    int s  = s_src[row];
    int dd = s_dst[row];

    // stage 2: m(lane's 4 dims) = b + t@w2 + A_src[s] + A_dst[dd]
    float4 acc = s_b[lane];
#pragma unroll
    for (int r = 0; r < RK; r++) {
        float tr = s_t[row][r];
        float4 w = s_w2[r * D4 + lane];
        acc.x = fmaf(tr, w.x, acc.x); acc.y = fmaf(tr, w.y, acc.y);
        acc.z = fmaf(tr, w.z, acc.z); acc.w = fmaf(tr, w.w, acc.w);
    }
    size_t so = (size_t)s * D4 + lane;
    size_t dof = (size_t)dd * D4 + lane;
    float4 a  = g_Asrc[so];
    float4 b2 = g_Adst[dof];
    float4 bh = g_Abh [so];
    acc.x += a.x + b2.x; acc.y += a.y + b2.y;
    acc.z += a.z + b2.z; acc.w += a.w + b2.w;

    float4 sg;
    sg.x = sigm(acc.x); sg.y = sigm(acc.y); sg.z = sigm(acc.z); sg.w = sigm(acc.w);

    if (valid) {
        red_add_v4(&g_Ss[dof], sg);
        float4 shv = make_float4(bh.x * sg.x, bh.y * sg.y, bh.z * sg.z, bh.w * sg.w);
        red_add_v4(&g_Sh[dof], shv);
    }

    // LayerNorm stats across the 16 lanes of this edge
    float sum = acc.x + acc.y + acc.z + acc.w;
    float ssq = acc.x*acc.x + acc.y*acc.y + acc.z*acc.z + acc.w*acc.w;
#pragma unroll
    for (int off = 8; off; off >>= 1) {
        sum += __shfl_xor_sync(0xffffffffu, sum, off);
        ssq += __shfl_xor_sync(0xffffffffu, ssq, off);
    }
    float mu   = sum * (1.0f / D);
    float rstd = rsqrtf(fmaf(-mu, mu, ssq * (1.0f / D)) + 1e-5f);

    float4 gg = s_g[lane], lb = s_lb[lane], xe = s_x[row][lane];
    float v0 = (acc.x - mu) * rstd * gg.x + lb.x;
    float v1 = (acc.y - mu) * rstd * gg.y + lb.y;
    float v2 = (acc.z - mu) * rstd * gg.z + lb.z;
    float v3 = (acc.w - mu) * rstd * gg.w + lb.w;
    float4 o;
    o.x = v0 * sigm(v0) + xe.x;
    o.y = v1 * sigm(v1) + xe.y;
    o.z = v2 * sigm(v2) + xe.z;
    o.w = v3 * sigm(v3) + xe.w;
    if (valid) ((float4*)yout)[(size_t)e * D4 + lane] = o;
}

// ------------------------------------------------------------- node update
__global__ void __launch_bounds__(256) k_nodeupd(
    const float* __restrict__ nf,
    const float* __restrict__ w1, const float* __restrict__ w2, const float* __restrict__ bias,
    const float* __restrict__ lng, const float* __restrict__ lnb,
    float* __restrict__ xout, int N)
{
    __shared__ float  s_w1[D * RK];
    __shared__ float4 s_w2[RK * D4];
    __shared__ float4 s_b[D4], s_g[D4], s_lb[D4];
    __shared__ float4 s_x[16][D4];
    __shared__ float  s_t[16][RK];

    int tid = threadIdx.x;
    for (int i = tid; i < D * RK; i += 256) {
        s_w1[i] = w1[i];
        ((float*)s_w2)[i] = w2[i];
    }
    if (tid < D) {
        ((float*)s_b)[tid] = bias[tid];
        ((float*)s_g)[tid] = lng[tid];
        ((float*)s_lb)[tid] = lnb[tid];
    }
    {
        int idx = blockIdx.x * 256 + tid;
        if (idx < N * D4) s_x[tid >> 4][tid & 15] = ((const float4*)nf)[idx];
    }
    __syncthreads();

    int row = tid >> 4, lane = tid & 15;
    int n = blockIdx.x * 16 + row;
    bool valid = (n < N);
    int n_cl = min(n, N - 1);

    const float* xr = (const float*)s_x[row];
    float t = 0.f;
#pragma unroll
    for (int k = 0; k < D; k++) t = fmaf(xr[k], s_w1[k * RK + lane], t);
    s_t[row][lane] = t;
    __syncthreads();

    float4 acc = s_b[lane];
#pragma unroll
    for (int r = 0; r < RK; r++) {
        float tr = s_t[row][r];
        float4 w = s_w2[r * D4 + lane];
        acc.x = fmaf(tr, w.x, acc.x); acc.y = fmaf(tr, w.y, acc.y);
        acc.z = fmaf(tr, w.z, acc.z); acc.w = fmaf(tr, w.w, acc.w);
    }
    size_t o = (size_t)n_cl * D4 + lane;
    float4 hn = g_Sh[o];
    float4 hd = g_Ss[o];
    acc.x += hn.x * __fdividef(1.f, hd.x + 1e-6f);
    acc.y += hn.y * __fdividef(1.f, hd.y + 1e-6f);
    acc.z += hn.z * __fdividef(1.f, hd.z + 1e-6f);
    acc.w += hn.w * __fdividef(1.f, hd.w + 1e-6f);

    float sum = acc.x + acc.y + acc.z + acc.w;
    float ssq = acc.x*acc.x + acc.y*acc.y + acc.z*acc.z + acc.w*acc.w;
#pragma unroll
    for (int off = 8; off; off >>= 1) {
        sum += __shfl_xor_sync(0xffffffffu, sum, off);
        ssq += __shfl_xor_sync(0xffffffffu, ssq, off);
    }
    float mu   = sum * (1.0f / D);
    float rstd = rsqrtf(fmaf(-mu, mu, ssq * (1.0f / D)) + 1e-5f);

    float4 gg = s_g[lane], lb = s_lb[lane], xn = s_x[row][lane];
    float v0 = (acc.x - mu) * rstd * gg.x + lb.x;
    float v1 = (acc.y - mu) * rstd * gg.y + lb.y;
    float v2 = (acc.z - mu) * rstd * gg.z + lb.z;
    float v3 = (acc.w - mu) * rstd * gg.w + lb.w;
    float4 ov;
    ov.x = v0 * sigm(v0) + xn.x;
    ov.y = v1 * sigm(v1) + xn.y;
    ov.z = v2 * sigm(v2) + xn.z;
    ov.w = v3 * sigm(v3) + xn.w;
    if (valid) ((float4*)xout)[(size_t)n * D4 + lane] = ov;
}

// ---------------------------------------------------------------------- launch
extern "C" void kernel_launch(void* const* d_in, const int* in_sizes, int n_in,
                              void* d_out, int out_size)
{
    const float* nf  = (const float*)d_in[0];
    const float* ef  = (const float*)d_in[1];
    const int*   src = (const int*)d_in[2];
    const int*   dst = (const int*)d_in[3];
    const float* sgw1 = (const float*)d_in[4];
    const float* sgw2 = (const float*)d_in[5];
    const float* sgb  = (const float*)d_in[6];
    const float* dgw1 = (const float*)d_in[7];
    const float* dgw2 = (const float*)d_in[8];
    const float* dgb  = (const float*)d_in[9];
    const float* egw1 = (const float*)d_in[10];
    const float* egw2 = (const float*)d_in[11];
    const float* egb  = (const float*)d_in[12];
    const float* suw1 = (const float*)d_in[13];
    const float* suw2 = (const float*)d_in[14];
    const float* sub  = (const float*)d_in[15];
    const float* duw1 = (const float*)d_in[16];
    const float* duw2 = (const float*)d_in[17];
    const float* dub  = (const float*)d_in[18];
    const float* ln_n_g = (const float*)d_in[19];
    const float* ln_n_b = (const float*)d_in[20];
    const float* ln_e_g = (const float*)d_in[21];
    const float* ln_e_b = (const float*)d_in[22];

    int N = in_sizes[0] / D;
    int E = in_sizes[2];

    float* xout = (float*)d_out;
    float* yout = xout + (size_t)N * D;

    k_zero<<<1024, 256>>>(N * D4);
    k_nodepre<<<(N + 15) / 16, 256>>>(nf, N,
                                      sgw1, sgw2, sgb,
                                      dgw1, dgw2, dgb,
                                      duw1, duw2, dub);
    k_edge<<<(E + 15) / 16, 256>>>(ef, src, dst,
                                   egw1, egw2, egb,
                                   ln_e_g, ln_e_b, yout, E);
    k_nodeupd<<<(N + 15) / 16, 256>>>(nf, suw1, suw2, sub,
                                      ln_n_g, ln_n_b, xout, N);
}

// round 3
// speedup vs baseline: 3.1851x; 1.2605x over previous
#include <cuda_runtime.h>

#define D    64
#define D4   16
#define RK   16
#define MAXN 100000

typedef unsigned long long ull;

// Scratch (allocation-free rule: __device__ globals). float4 for 16B alignment.
static __device__ float4 g_Asrc[(size_t)MAXN * D4];
static __device__ float4 g_Adst[(size_t)MAXN * D4];
static __device__ float4 g_Abh [(size_t)MAXN * D4];
static __device__ float4 g_Sh  [(size_t)MAXN * D4];
static __device__ float4 g_Ss  [(size_t)MAXN * D4];

__device__ __forceinline__ float sigm(float x) {
    return __fdividef(1.0f, 1.0f + __expf(-x));
}
__device__ __forceinline__ void red_add_v4(float4* p, float4 v) {
    asm volatile("red.global.add.v4.f32 [%0], {%1,%2,%3,%4};"
                 :: "l"(p), "f"(v.x), "f"(v.y), "f"(v.z), "f"(v.w) : "memory");
}
// packed fp32x2 helpers (sm_100+)
__device__ __forceinline__ ull pk2(float lo, float hi) {
    ull r; asm("mov.b64 %0,{%1,%2};" : "=l"(r) : "f"(lo), "f"(hi)); return r;
}
__device__ __forceinline__ void upk2(ull v, float& lo, float& hi) {
    asm("mov.b64 {%0,%1},%2;" : "=f"(lo), "=f"(hi) : "l"(v));
}
__device__ __forceinline__ ull fma2(ull a, ull b, ull c) {
    ull d; asm("fma.rn.f32x2 %0,%1,%2,%3;" : "=l"(d) : "l"(a), "l"(b), "l"(c)); return d;
}
__device__ __forceinline__ ull add2(ull a, ull b) {
    ull d; asm("add.rn.f32x2 %0,%1,%2;" : "=l"(d) : "l"(a), "l"(b)); return d;
}

// ------------------------------------------------- node precompute (3 gates)
__global__ void __launch_bounds__(256) k_nodepre(
    const float* __restrict__ nf, int N,
    const float* __restrict__ w1a, const float* __restrict__ w2a, const float* __restrict__ ba,
    const float* __restrict__ w1b, const float* __restrict__ w2b, const float* __restrict__ bb,
    const float* __restrict__ w1c, const float* __restrict__ w2c, const float* __restrict__ bc)
{
    __shared__ float4 s_w1t[3][RK][D4 + 1];
    __shared__ float4 s_w2[3][RK * D4];
    __shared__ float4 s_b[3][D4];
    __shared__ float4 s_x[16][D4 + 1];

    int tid = threadIdx.x;
    for (int i = tid; i < D * RK; i += 256) {
        int k = i >> 4, r = i & 15;
        ((float*)&s_w1t[0][r][k >> 2])[k & 3] = w1a[i];
        ((float*)&s_w1t[1][r][k >> 2])[k & 3] = w1b[i];
        ((float*)&s_w1t[2][r][k >> 2])[k & 3] = w1c[i];
        ((float*)s_w2[0])[i] = w2a[i];
        ((float*)s_w2[1])[i] = w2b[i];
        ((float*)s_w2[2])[i] = w2c[i];
    }
    if (tid < D) {
        ((float*)s_b[0])[tid] = ba[tid];
        ((float*)s_b[1])[tid] = bb[tid];
        ((float*)s_b[2])[tid] = bc[tid];
    }
    __syncthreads();

    {   // fused zero of Sh/Ss
        size_t idx = (size_t)blockIdx.x * 256 + tid;
        if (idx < (size_t)N * D4) {
            float4 z = make_float4(0.f, 0.f, 0.f, 0.f);
            g_Sh[idx] = z; g_Ss[idx] = z;
        }
    }

    int row = tid >> 4, lane = tid & 15;
    int n = blockIdx.x * 16 + row;
    {
        size_t idx = (size_t)blockIdx.x * 256 + tid;
        size_t lim = (size_t)N * D4;
        s_x[row][lane] = ((const float4*)nf)[idx < lim ? idx : lim - 1];
    }
    __syncwarp();

    ull p0 = 0, p1 = 0, p2 = 0;
#pragma unroll
    for (int k4 = 0; k4 < D4; k4++) {
        ulonglong2 xv = *(const ulonglong2*)&s_x[row][k4];
        ulonglong2 w0 = *(const ulonglong2*)&s_w1t[0][lane][k4];
        ulonglong2 w1_ = *(const ulonglong2*)&s_w1t[1][lane][k4];
        ulonglong2 w2_ = *(const ulonglong2*)&s_w1t[2][lane][k4];
        p0 = fma2(xv.x, w0.x, p0);  p0 = fma2(xv.y, w0.y, p0);
        p1 = fma2(xv.x, w1_.x, p1); p1 = fma2(xv.y, w1_.y, p1);
        p2 = fma2(xv.x, w2_.x, p2); p2 = fma2(xv.y, w2_.y, p2);
    }
    float t0, t1, t2;
    { float a, b;
      upk2(p0, a, b); t0 = a + b;
      upk2(p1, a, b); t1 = a + b;
      upk2(p2, a, b); t2 = a + b; }

    ulonglong2 b0 = *(const ulonglong2*)&s_b[0][lane];
    ulonglong2 b1 = *(const ulonglong2*)&s_b[1][lane];
    ulonglong2 b2 = *(const ulonglong2*)&s_b[2][lane];
    ull a00 = b0.x, a01 = b0.y, a10 = b1.x, a11 = b1.y, a20 = b2.x, a21 = b2.y;
#pragma unroll
    for (int r = 0; r < RK; r++) {
        float u0 = __shfl_sync(0xffffffffu, t0, r, 16);
        float u1 = __shfl_sync(0xffffffffu, t1, r, 16);
        float u2 = __shfl_sync(0xffffffffu, t2, r, 16);
        ull u0p = pk2(u0, u0), u1p = pk2(u1, u1), u2p = pk2(u2, u2);
        ulonglong2 w0 = *(const ulonglong2*)&s_w2[0][r * D4 + lane];
        ulonglong2 w1_ = *(const ulonglong2*)&s_w2[1][r * D4 + lane];
        ulonglong2 w2_ = *(const ulonglong2*)&s_w2[2][r * D4 + lane];
        a00 = fma2(u0p, w0.x, a00);  a01 = fma2(u0p, w0.y, a01);
        a10 = fma2(u1p, w1_.x, a10); a11 = fma2(u1p, w1_.y, a11);
        a20 = fma2(u2p, w2_.x, a20); a21 = fma2(u2p, w2_.y, a21);
    }
    if (n < N) {
        size_t o = (size_t)n * D4 + lane;
        *(ulonglong2*)&g_Asrc[o] = make_ulonglong2(a00, a01);
        *(ulonglong2*)&g_Adst[o] = make_ulonglong2(a10, a11);
        *(ulonglong2*)&g_Abh [o] = make_ulonglong2(a20, a21);
    }
}

// ------------------------------------------------------------------ edge pass
__global__ void __launch_bounds__(256) k_edge(
    const float* __restrict__ ef, const int* __restrict__ src, const int* __restrict__ dst,
    const float* __restrict__ w1, const float* __restrict__ w2, const float* __restrict__ bias,
    const float* __restrict__ lng, const float* __restrict__ lnb,
    float* __restrict__ yout, int E)
{
    __shared__ float4 s_w1t[RK][D4 + 1];
    __shared__ float4 s_w2[RK * D4];
    __shared__ float4 s_b[D4], s_g[D4], s_lb[D4];
    __shared__ float4 s_x[32][D4 + 1];

    int tid = threadIdx.x;
    for (int i = tid; i < D * RK; i += 256) {
        int k = i >> 4, r = i & 15;
        ((float*)&s_w1t[r][k >> 2])[k & 3] = w1[i];
        ((float*)s_w2)[i] = w2[i];
    }
    if (tid < D) {
        ((float*)s_b)[tid]  = bias[tid];
        ((float*)s_g)[tid]  = lng[tid];
        ((float*)s_lb)[tid] = lnb[tid];
    }
    __syncthreads();

    int warp = tid >> 5, l = tid & 31;
    int row = tid >> 4, lane = tid & 15;
    size_t e0 = (size_t)blockIdx.x * 32;

    {
        size_t base = e0 * D4 + (size_t)warp * 64;
        size_t lim = (size_t)E * D4;
        size_t i1 = base + l, i2 = base + 32 + l;
        float4 v1 = ((const float4*)ef)[i1 < lim ? i1 : lim - 1];
        float4 v2 = ((const float4*)ef)[i2 < lim ? i2 : lim - 1];
        s_x[warp * 4 + (l >> 4)][l & 15]     = v1;
        s_x[warp * 4 + 2 + (l >> 4)][l & 15] = v2;
    }
    __syncwarp();

    int rA = 2 * row, rB = 2 * row + 1;

    ull pA = 0, pB = 0;
#pragma unroll
    for (int k4 = 0; k4 < D4; k4++) {
        ulonglong2 wv = *(const ulonglong2*)&s_w1t[lane][k4];
        ulonglong2 xa = *(const ulonglong2*)&s_x[rA][k4];
        ulonglong2 xb = *(const ulonglong2*)&s_x[rB][k4];
        pA = fma2(xa.x, wv.x, pA); pA = fma2(xa.y, wv.y, pA);
        pB = fma2(xb.x, wv.x, pB); pB = fma2(xb.y, wv.y, pB);
    }
    float tA, tB;
    { float a, b; upk2(pA, a, b); tA = a + b; upk2(pB, a, b); tB = a + b; }

    ulonglong2 bb = *(const ulonglong2*)&s_b[lane];
    ull accA0 = bb.x, accA1 = bb.y, accB0 = bb.x, accB1 = bb.y;
#pragma unroll
    for (int r = 0; r < RK; r++) {
        float trA = __shfl_sync(0xffffffffu, tA, r, 16);
        float trB = __shfl_sync(0xffffffffu, tB, r, 16);
        ulonglong2 w = *(const ulonglong2*)&s_w2[r * D4 + lane];
        ull ta = pk2(trA, trA), tb = pk2(trB, trB);
        accA0 = fma2(ta, w.x, accA0); accA1 = fma2(ta, w.y, accA1);
        accB0 = fma2(tb, w.x, accB0); accB1 = fma2(tb, w.y, accB1);
    }

    size_t eA = e0 + rA, eB = e0 + rB;
    size_t eAc = eA < (size_t)E ? eA : (size_t)E - 1;
    size_t eBc = eB < (size_t)E ? eB : (size_t)E - 1;
    int sA = src[eAc], dA = dst[eAc];
    int sB = src[eBc], dB = dst[eBc];
    size_t soA = (size_t)sA * D4 + lane, doA = (size_t)dA * D4 + lane;
    size_t soB = (size_t)sB * D4 + lane, doB = (size_t)dB * D4 + lane;

    ulonglong2 gsA = *(const ulonglong2*)&g_Asrc[soA];
    ulonglong2 gdA = *(const ulonglong2*)&g_Adst[doA];
    ulonglong2 ghA = *(const ulonglong2*)&g_Abh [soA];
    ulonglong2 gsB = *(const ulonglong2*)&g_Asrc[soB];
    ulonglong2 gdB = *(const ulonglong2*)&g_Adst[doB];
    ulonglong2 ghB = *(const ulonglong2*)&g_Abh [soB];

    accA0 = add2(accA0, add2(gsA.x, gdA.x));
    accA1 = add2(accA1, add2(gsA.y, gdA.y));
    accB0 = add2(accB0, add2(gsB.x, gdB.x));
    accB1 = add2(accB1, add2(gsB.y, gdB.y));

    float mA0, mA1, mA2, mA3, mB0, mB1, mB2, mB3;
    upk2(accA0, mA0, mA1); upk2(accA1, mA2, mA3);
    upk2(accB0, mB0, mB1); upk2(accB1, mB2, mB3);

    float gA0 = sigm(mA0), gA1 = sigm(mA1), gA2 = sigm(mA2), gA3 = sigm(mA3);
    float gB0 = sigm(mB0), gB1 = sigm(mB1), gB2 = sigm(mB2), gB3 = sigm(mB3);

    if (eA < (size_t)E) {
        float h0, h1, h2, h3;
        upk2(ghA.x, h0, h1); upk2(ghA.y, h2, h3);
        red_add_v4(&g_Ss[doA], make_float4(gA0, gA1, gA2, gA3));
        red_add_v4(&g_Sh[doA], make_float4(h0 * gA0, h1 * gA1, h2 * gA2, h3 * gA3));
    }
    if (eB < (size_t)E) {
        float h0, h1, h2, h3;
        upk2(ghB.x, h0, h1); upk2(ghB.y, h2, h3);
        red_add_v4(&g_Ss[doB], make_float4(gB0, gB1, gB2, gB3));
        red_add_v4(&g_Sh[doB], make_float4(h0 * gB0, h1 * gB1, h2 * gB2, h3 * gB3));
    }

    float sumA = mA0 + mA1 + mA2 + mA3;
    float ssqA = mA0*mA0 + mA1*mA1 + mA2*mA2 + mA3*mA3;
    float sumB = mB0 + mB1 + mB2 + mB3;
    float ssqB = mB0*mB0 + mB1*mB1 + mB2*mB2 + mB3*mB3;
#pragma unroll
    for (int off = 8; off; off >>= 1) {
        sumA += __shfl_xor_sync(0xffffffffu, sumA, off);
        ssqA += __shfl_xor_sync(0xffffffffu, ssqA, off);
        sumB += __shfl_xor_sync(0xffffffffu, sumB, off);
        ssqB += __shfl_xor_sync(0xffffffffu, ssqB, off);
    }
    float muA = sumA * (1.0f / D);
    float rsA = rsqrtf(fmaf(-muA, muA, ssqA * (1.0f / D)) + 1e-5f);
    float muB = sumB * (1.0f / D);
    float rsB = rsqrtf(fmaf(-muB, muB, ssqB * (1.0f / D)) + 1e-5f);

    float4 gg = s_g[lane], lb = s_lb[lane];
    float4 xeA = s_x[rA][lane], xeB = s_x[rB][lane];

    float v0 = (mA0 - muA) * rsA * gg.x + lb.x;
    float v1 = (mA1 - muA) * rsA * gg.y + lb.y;
    float v2 = (mA2 - muA) * rsA * gg.z + lb.z;
    float v3 = (mA3 - muA) * rsA * gg.w + lb.w;
    float4 oA = make_float4(v0 * sigm(v0) + xeA.x, v1 * sigm(v1) + xeA.y,
                            v2 * sigm(v2) + xeA.z, v3 * sigm(v3) + xeA.w);
    v0 = (mB0 - muB) * rsB * gg.x + lb.x;
    v1 = (mB1 - muB) * rsB * gg.y + lb.y;
    v2 = (mB2 - muB) * rsB * gg.z + lb.z;
    v3 = (mB3 - muB) * rsB * gg.w + lb.w;
    float4 oB = make_float4(v0 * sigm(v0) + xeB.x, v1 * sigm(v1) + xeB.y,
                            v2 * sigm(v2) + xeB.z, v3 * sigm(v3) + xeB.w);

    if (eA < (size_t)E) ((float4*)yout)[eA * D4 + lane] = oA;
    if (eB < (size_t)E) ((float4*)yout)[eB * D4 + lane] = oB;
}

// ------------------------------------------------------------- node update
__global__ void __launch_bounds__(256) k_nodeupd(
    const float* __restrict__ nf,
    const float* __restrict__ w1, const float* __restrict__ w2, const float* __restrict__ bias,
    const float* __restrict__ lng, const float* __restrict__ lnb,
    float* __restrict__ xout, int N)
{
    __shared__ float4 s_w1t[RK][D4 + 1];
    __shared__ float4 s_w2[RK * D4];
    __shared__ float4 s_b[D4], s_g[D4], s_lb[D4];
    __shared__ float4 s_x[16][D4 + 1];

    int tid = threadIdx.x;
    for (int i = tid; i < D * RK; i += 256) {
        int k = i >> 4, r = i & 15;
        ((float*)&s_w1t[r][k >> 2])[k & 3] = w1[i];
        ((float*)s_w2)[i] = w2[i];
    }
    if (tid < D) {
        ((float*)s_b)[tid]  = bias[tid];
        ((float*)s_g)[tid]  = lng[tid];
        ((float*)s_lb)[tid] = lnb[tid];
    }
    __syncthreads();

    int row = tid >> 4, lane = tid & 15;
    int n = blockIdx.x * 16 + row;
    {
        size_t idx = (size_t)blockIdx.x * 256 + tid;
        size_t lim = (size_t)N * D4;
        s_x[row][lane] = ((const float4*)nf)[idx < lim ? idx : lim - 1];
    }
    __syncwarp();

    ull p = 0;
#pragma unroll
    for (int k4 = 0; k4 < D4; k4++) {
        ulonglong2 xv = *(const ulonglong2*)&s_x[row][k4];
        ulonglong2 wv = *(const ulonglong2*)&s_w1t[lane][k4];
        p = fma2(xv.x, wv.x, p);
        p = fma2(xv.y, wv.y, p);
    }
    float t; { float a, b; upk2(p, a, b); t = a + b; }

    ulonglong2 bb = *(const ulonglong2*)&s_b[lane];
    ull acc0 = bb.x, acc1 = bb.y;
#pragma unroll
    for (int r = 0; r < RK; r++) {
        float u = __shfl_sync(0xffffffffu, t, r, 16);
        ull up = pk2(u, u);
        ulonglong2 w = *(const ulonglong2*)&s_w2[r * D4 + lane];
        acc0 = fma2(up, w.x, acc0);
        acc1 = fma2(up, w.y, acc1);
    }

    int n_cl = n < N ? n : N - 1;
    size_t o = (size_t)n_cl * D4 + lane;
    ulonglong2 hn = *(const ulonglong2*)&g_Sh[o];
    ulonglong2 hd = *(const ulonglong2*)&g_Ss[o];
    float m0, m1, m2, m3, q0, q1, q2, q3, d0, d1, d2, d3;
    upk2(acc0, m0, m1); upk2(acc1, m2, m3);
    upk2(hn.x, q0, q1); upk2(hn.y, q2, q3);
    upk2(hd.x, d0, d1); upk2(hd.y, d2, d3);
    m0 += q0 * __fdividef(1.f, d0 + 1e-6f);
    m1 += q1 * __fdividef(1.f, d1 + 1e-6f);
    m2 += q2 * __fdividef(1.f, d2 + 1e-6f);
    m3 += q3 * __fdividef(1.f, d3 + 1e-6f);

    float sum = m0 + m1 + m2 + m3;
    float ssq = m0*m0 + m1*m1 + m2*m2 + m3*m3;
#pragma unroll
    for (int off = 8; off; off >>= 1) {
        sum += __shfl_xor_sync(0xffffffffu, sum, off);
        ssq += __shfl_xor_sync(0xffffffffu, ssq, off);
    }
    float mu = sum * (1.0f / D);
    float rstd = rsqrtf(fmaf(-mu, mu, ssq * (1.0f / D)) + 1e-5f);

    float4 gg = s_g[lane], lb = s_lb[lane], xn = s_x[row][lane];
    float v0 = (m0 - mu) * rstd * gg.x + lb.x;
    float v1 = (m1 - mu) * rstd * gg.y + lb.y;
    float v2 = (m2 - mu) * rstd * gg.z + lb.z;
    float v3 = (m3 - mu) * rstd * gg.w + lb.w;
    float4 ov = make_float4(v0 * sigm(v0) + xn.x, v1 * sigm(v1) + xn.y,
                            v2 * sigm(v2) + xn.z, v3 * sigm(v3) + xn.w);
    if (n < N) ((float4*)xout)[(size_t)n * D4 + lane] = ov;
}

// ---------------------------------------------------------------------- launch
extern "C" void kernel_launch(void* const* d_in, const int* in_sizes, int n_in,
                              void* d_out, int out_size)
{
    const float* nf  = (const float*)d_in[0];
    const float* ef  = (const float*)d_in[1];
    const int*   src = (const int*)d_in[2];
    const int*   dst = (const int*)d_in[3];
    const float* sgw1 = (const float*)d_in[4];
    const float* sgw2 = (const float*)d_in[5];
    const float* sgb  = (const float*)d_in[6];
    const float* dgw1 = (const float*)d_in[7];
    const float* dgw2 = (const float*)d_in[8];
    const float* dgb  = (const float*)d_in[9];
    const float* egw1 = (const float*)d_in[10];
    const float* egw2 = (const float*)d_in[11];
    const float* egb  = (const float*)d_in[12];
    const float* suw1 = (const float*)d_in[13];
    const float* suw2 = (const float*)d_in[14];
    const float* sub  = (const float*)d_in[15];
    const float* duw1 = (const float*)d_in[16];
    const float* duw2 = (const float*)d_in[17];
    const float* dub  = (const float*)d_in[18];
    const float* ln_n_g = (const float*)d_in[19];
    const float* ln_n_b = (const float*)d_in[20];
    const float* ln_e_g = (const float*)d_in[21];
    const float* ln_e_b = (const float*)d_in[22];

    int N = in_sizes[0] / D;
    int E = in_sizes[2];

    float* xout = (float*)d_out;
    float* yout = xout + (size_t)N * D;

    k_nodepre<<<(N + 15) / 16, 256>>>(nf, N,
                                      sgw1, sgw2, sgb,
                                      dgw1, dgw2, dgb,
                                      duw1, duw2, dub);
    k_edge<<<(E + 31) / 32, 256>>>(ef, src, dst,
                                   egw1, egw2, egb,
                                   ln_e_g, ln_e_b, yout, E);
    k_nodeupd<<<(N + 15) / 16, 256>>>(nf, suw1, suw2, sub,
                                      ln_n_g, ln_n_b, xout, N);
}

// round 4
// speedup vs baseline: 3.3854x; 1.0629x over previous
#include <cuda_runtime.h>

#define D    64
#define D4   16
#define RK   16
#define MAXN 100000

typedef unsigned long long ull;

// Scratch (allocation-free rule: __device__ globals). float4 for 16B alignment.
static __device__ float4 g_Asrc[(size_t)MAXN * D4];
static __device__ float4 g_Adst[(size_t)MAXN * D4];
static __device__ float4 g_Abh [(size_t)MAXN * D4];
static __device__ float4 g_Sh  [(size_t)MAXN * D4];
static __device__ float4 g_Ss  [(size_t)MAXN * D4];

__device__ __forceinline__ float sigm(float x) {
    return __fdividef(1.0f, 1.0f + __expf(-x));
}
__device__ __forceinline__ void red_add_v4(float4* p, float4 v) {
    asm volatile("red.global.add.v4.f32 [%0], {%1,%2,%3,%4};"
                 :: "l"(p), "f"(v.x), "f"(v.y), "f"(v.z), "f"(v.w) : "memory");
}
// packed fp32x2 helpers (sm_100+)
__device__ __forceinline__ ull pk2(float lo, float hi) {
    ull r; asm("mov.b64 %0,{%1,%2};" : "=l"(r) : "f"(lo), "f"(hi)); return r;
}
__device__ __forceinline__ void upk2(ull v, float& lo, float& hi) {
    asm("mov.b64 {%0,%1},%2;" : "=f"(lo), "=f"(hi) : "l"(v));
}
__device__ __forceinline__ ull fma2(ull a, ull b, ull c) {
    ull d; asm("fma.rn.f32x2 %0,%1,%2,%3;" : "=l"(d) : "l"(a), "l"(b), "l"(c)); return d;
}
__device__ __forceinline__ ull add2(ull a, ull b) {
    ull d; asm("add.rn.f32x2 %0,%1,%2;" : "=l"(d) : "l"(a), "l"(b)); return d;
}

#define NBLK 592

// ------------------------------------------------- node precompute (3 gates)
// persistent blocks; weights loaded once; chunks of 16 nodes.
__global__ void __launch_bounds__(256) k_nodepre(
    const float* __restrict__ nf, int N, int nChunks,
    const float* __restrict__ w1a, const float* __restrict__ w2a, const float* __restrict__ ba,
    const float* __restrict__ w1b, const float* __restrict__ w2b, const float* __restrict__ bb,
    const float* __restrict__ w1c, const float* __restrict__ w2c, const float* __restrict__ bc)
{
    __shared__ float4 s_w1t[3][RK][D4 + 1];
    __shared__ float4 s_w2[3][RK * D4];
    __shared__ float4 s_b[3][D4];
    __shared__ float4 s_x[16][D4 + 1];

    int tid = threadIdx.x;
    for (int i = tid; i < D * RK; i += 256) {
        int k = i >> 4, r = i & 15;
        ((float*)&s_w1t[0][r][k >> 2])[k & 3] = w1a[i];
        ((float*)&s_w1t[1][r][k >> 2])[k & 3] = w1b[i];
        ((float*)&s_w1t[2][r][k >> 2])[k & 3] = w1c[i];
        ((float*)s_w2[0])[i] = w2a[i];
        ((float*)s_w2[1])[i] = w2b[i];
        ((float*)s_w2[2])[i] = w2c[i];
    }
    if (tid < D) {
        ((float*)s_b[0])[tid] = ba[tid];
        ((float*)s_b[1])[tid] = bb[tid];
        ((float*)s_b[2])[tid] = bc[tid];
    }
    __syncthreads();

    int row = tid >> 4, lane = tid & 15;
    size_t lim = (size_t)N * D4;
    float4 z = make_float4(0.f, 0.f, 0.f, 0.f);

    for (int c = blockIdx.x; c < nChunks; c += gridDim.x) {
        size_t idx = (size_t)c * 256 + tid;
        if (idx < lim) { g_Sh[idx] = z; g_Ss[idx] = z; }

        __syncwarp();
        s_x[row][lane] = ((const float4*)nf)[idx < lim ? idx : lim - 1];
        __syncwarp();

        ull p0 = 0, p1 = 0, p2 = 0;
#pragma unroll
        for (int k4 = 0; k4 < D4; k4++) {
            ulonglong2 xv = *(const ulonglong2*)&s_x[row][k4];
            ulonglong2 w0 = *(const ulonglong2*)&s_w1t[0][lane][k4];
            ulonglong2 w1_ = *(const ulonglong2*)&s_w1t[1][lane][k4];
            ulonglong2 w2_ = *(const ulonglong2*)&s_w1t[2][lane][k4];
            p0 = fma2(xv.x, w0.x, p0);  p0 = fma2(xv.y, w0.y, p0);
            p1 = fma2(xv.x, w1_.x, p1); p1 = fma2(xv.y, w1_.y, p1);
            p2 = fma2(xv.x, w2_.x, p2); p2 = fma2(xv.y, w2_.y, p2);
        }
        float t0, t1, t2;
        { float a, b;
          upk2(p0, a, b); t0 = a + b;
          upk2(p1, a, b); t1 = a + b;
          upk2(p2, a, b); t2 = a + b; }

        ulonglong2 b0 = *(const ulonglong2*)&s_b[0][lane];
        ulonglong2 b1 = *(const ulonglong2*)&s_b[1][lane];
        ulonglong2 b2 = *(const ulonglong2*)&s_b[2][lane];
        ull a00 = b0.x, a01 = b0.y, a10 = b1.x, a11 = b1.y, a20 = b2.x, a21 = b2.y;
#pragma unroll
        for (int r = 0; r < RK; r++) {
            float u0 = __shfl_sync(0xffffffffu, t0, r, 16);
            float u1 = __shfl_sync(0xffffffffu, t1, r, 16);
            float u2 = __shfl_sync(0xffffffffu, t2, r, 16);
            ull u0p = pk2(u0, u0), u1p = pk2(u1, u1), u2p = pk2(u2, u2);
            ulonglong2 w0 = *(const ulonglong2*)&s_w2[0][r * D4 + lane];
            ulonglong2 w1_ = *(const ulonglong2*)&s_w2[1][r * D4 + lane];
            ulonglong2 w2_ = *(const ulonglong2*)&s_w2[2][r * D4 + lane];
            a00 = fma2(u0p, w0.x, a00);  a01 = fma2(u0p, w0.y, a01);
            a10 = fma2(u1p, w1_.x, a10); a11 = fma2(u1p, w1_.y, a11);
            a20 = fma2(u2p, w2_.x, a20); a21 = fma2(u2p, w2_.y, a21);
        }
        int n = c * 16 + row;
        if (n < N) {
            size_t o = (size_t)n * D4 + lane;
            *(ulonglong2*)&g_Asrc[o] = make_ulonglong2(a00, a01);
            *(ulonglong2*)&g_Adst[o] = make_ulonglong2(a10, a11);
            *(ulonglong2*)&g_Abh [o] = make_ulonglong2(a20, a21);
        }
    }
}

// ------------------------------------------------------------------ edge pass
// persistent blocks; chunks of 32 edges; gathers issued before compute.
__global__ void __launch_bounds__(256) k_edge(
    const float* __restrict__ ef, const int* __restrict__ src, const int* __restrict__ dst,
    const float* __restrict__ w1, const float* __restrict__ w2, const float* __restrict__ bias,
    const float* __restrict__ lng, const float* __restrict__ lnb,
    float* __restrict__ yout, int E, int nChunks)
{
    __shared__ float4 s_w1t[RK][D4 + 1];
    __shared__ float4 s_w2[RK * D4];
    __shared__ float4 s_b[D4], s_g[D4], s_lb[D4];
    __shared__ float4 s_x[32][D4 + 1];

    int tid = threadIdx.x;
    for (int i = tid; i < D * RK; i += 256) {
        int k = i >> 4, r = i & 15;
        ((float*)&s_w1t[r][k >> 2])[k & 3] = w1[i];
        ((float*)s_w2)[i] = w2[i];
    }
    if (tid < D) {
        ((float*)s_b)[tid]  = bias[tid];
        ((float*)s_g)[tid]  = lng[tid];
        ((float*)s_lb)[tid] = lnb[tid];
    }
    __syncthreads();

    int warp = tid >> 5, l = tid & 31;
    int row = tid >> 4, lane = tid & 15;
    int rA = 2 * row, rB = 2 * row + 1;
    size_t limE = (size_t)E;
    size_t lim4 = limE * D4;

    for (int c = blockIdx.x; c < nChunks; c += gridDim.x) {
        size_t e0 = (size_t)c * 32;

        // warp-local staging of this warp's 4 edge rows
        __syncwarp();
        {
            size_t base = e0 * D4 + (size_t)warp * 64;
            size_t i1 = base + l, i2 = base + 32 + l;
            float4 v1 = ((const float4*)ef)[i1 < lim4 ? i1 : lim4 - 1];
            float4 v2 = ((const float4*)ef)[i2 < lim4 ? i2 : lim4 - 1];
            s_x[warp * 4 + (l >> 4)][l & 15]     = v1;
            s_x[warp * 4 + 2 + (l >> 4)][l & 15] = v2;
        }

        // indices + gathers issued EARLY so L2 latency overlaps compute below
        size_t eA = e0 + rA, eB = e0 + rB;
        size_t eAc = eA < limE ? eA : limE - 1;
        size_t eBc = eB < limE ? eB : limE - 1;
        int sA = src[eAc], dA = dst[eAc];
        int sB = src[eBc], dB = dst[eBc];
        size_t soA = (size_t)sA * D4 + lane, doA = (size_t)dA * D4 + lane;
        size_t soB = (size_t)sB * D4 + lane, doB = (size_t)dB * D4 + lane;

        ulonglong2 gsA = *(const ulonglong2*)&g_Asrc[soA];
        ulonglong2 gdA = *(const ulonglong2*)&g_Adst[doA];
        ulonglong2 ghA = *(const ulonglong2*)&g_Abh [soA];
        ulonglong2 gsB = *(const ulonglong2*)&g_Asrc[soB];
        ulonglong2 gdB = *(const ulonglong2*)&g_Adst[doB];
        ulonglong2 ghB = *(const ulonglong2*)&g_Abh [soB];

        __syncwarp();

        // stage 1: t = xe @ w1
        ull pA = 0, pB = 0;
#pragma unroll
        for (int k4 = 0; k4 < D4; k4++) {
            ulonglong2 wv = *(const ulonglong2*)&s_w1t[lane][k4];
            ulonglong2 xa = *(const ulonglong2*)&s_x[rA][k4];
            ulonglong2 xb = *(const ulonglong2*)&s_x[rB][k4];
            pA = fma2(xa.x, wv.x, pA); pA = fma2(xa.y, wv.y, pA);
            pB = fma2(xb.x, wv.x, pB); pB = fma2(xb.y, wv.y, pB);
        }
        float tA, tB;
        { float a, b; upk2(pA, a, b); tA = a + b; upk2(pB, a, b); tB = a + b; }

        // stage 2: acc = b + t @ w2
        ulonglong2 bb = *(const ulonglong2*)&s_b[lane];
        ull accA0 = bb.x, accA1 = bb.y, accB0 = bb.x, accB1 = bb.y;
#pragma unroll
        for (int r = 0; r < RK; r++) {
            float trA = __shfl_sync(0xffffffffu, tA, r, 16);
            float trB = __shfl_sync(0xffffffffu, tB, r, 16);
            ulonglong2 w = *(const ulonglong2*)&s_w2[r * D4 + lane];
            ull ta = pk2(trA, trA), tb = pk2(trB, trB);
            accA0 = fma2(ta, w.x, accA0); accA1 = fma2(ta, w.y, accA1);
            accB0 = fma2(tb, w.x, accB0); accB1 = fma2(tb, w.y, accB1);
        }

        accA0 = add2(accA0, add2(gsA.x, gdA.x));
        accA1 = add2(accA1, add2(gsA.y, gdA.y));
        accB0 = add2(accB0, add2(gsB.x, gdB.x));
        accB1 = add2(accB1, add2(gsB.y, gdB.y));

        float mA0, mA1, mA2, mA3, mB0, mB1, mB2, mB3;
        upk2(accA0, mA0, mA1); upk2(accA1, mA2, mA3);
        upk2(accB0, mB0, mB1); upk2(accB1, mB2, mB3);

        float gA0 = sigm(mA0), gA1 = sigm(mA1), gA2 = sigm(mA2), gA3 = sigm(mA3);
        float gB0 = sigm(mB0), gB1 = sigm(mB1), gB2 = sigm(mB2), gB3 = sigm(mB3);

        if (eA < limE) {
            float h0, h1, h2, h3;
            upk2(ghA.x, h0, h1); upk2(ghA.y, h2, h3);
            red_add_v4(&g_Ss[doA], make_float4(gA0, gA1, gA2, gA3));
            red_add_v4(&g_Sh[doA], make_float4(h0 * gA0, h1 * gA1, h2 * gA2, h3 * gA3));
        }
        if (eB < limE) {
            float h0, h1, h2, h3;
            upk2(ghB.x, h0, h1); upk2(ghB.y, h2, h3);
            red_add_v4(&g_Ss[doB], make_float4(gB0, gB1, gB2, gB3));
            red_add_v4(&g_Sh[doB], make_float4(h0 * gB0, h1 * gB1, h2 * gB2, h3 * gB3));
        }

        float sumA = mA0 + mA1 + mA2 + mA3;
        float ssqA = mA0*mA0 + mA1*mA1 + mA2*mA2 + mA3*mA3;
        float sumB = mB0 + mB1 + mB2 + mB3;
        float ssqB = mB0*mB0 + mB1*mB1 + mB2*mB2 + mB3*mB3;
#pragma unroll
        for (int off = 8; off; off >>= 1) {
            sumA += __shfl_xor_sync(0xffffffffu, sumA, off);
            ssqA += __shfl_xor_sync(0xffffffffu, ssqA, off);
            sumB += __shfl_xor_sync(0xffffffffu, sumB, off);
            ssqB += __shfl_xor_sync(0xffffffffu, ssqB, off);
        }
        float muA = sumA * (1.0f / D);
        float rsA = rsqrtf(fmaf(-muA, muA, ssqA * (1.0f / D)) + 1e-5f);
        float muB = sumB * (1.0f / D);
        float rsB = rsqrtf(fmaf(-muB, muB, ssqB * (1.0f / D)) + 1e-5f);

        float4 gg = s_g[lane], lb = s_lb[lane];
        float4 xeA = s_x[rA][lane], xeB = s_x[rB][lane];

        float v0 = (mA0 - muA) * rsA * gg.x + lb.x;
        float v1 = (mA1 - muA) * rsA * gg.y + lb.y;
        float v2 = (mA2 - muA) * rsA * gg.z + lb.z;
        float v3 = (mA3 - muA) * rsA * gg.w + lb.w;
        float4 oA = make_float4(v0 * sigm(v0) + xeA.x, v1 * sigm(v1) + xeA.y,
                                v2 * sigm(v2) + xeA.z, v3 * sigm(v3) + xeA.w);
        v0 = (mB0 - muB) * rsB * gg.x + lb.x;
        v1 = (mB1 - muB) * rsB * gg.y + lb.y;
        v2 = (mB2 - muB) * rsB * gg.z + lb.z;
        v3 = (mB3 - muB) * rsB * gg.w + lb.w;
        float4 oB = make_float4(v0 * sigm(v0) + xeB.x, v1 * sigm(v1) + xeB.y,
                                v2 * sigm(v2) + xeB.z, v3 * sigm(v3) + xeB.w);

        if (eA < limE) ((float4*)yout)[eA * D4 + lane] = oA;
        if (eB < limE) ((float4*)yout)[eB * D4 + lane] = oB;
    }
}

// ------------------------------------------------------------- node update
__global__ void __launch_bounds__(256) k_nodeupd(
    const float* __restrict__ nf,
    const float* __restrict__ w1, const float* __restrict__ w2, const float* __restrict__ bias,
    const float* __restrict__ lng, const float* __restrict__ lnb,
    float* __restrict__ xout, int N, int nChunks)
{
    __shared__ float4 s_w1t[RK][D4 + 1];
    __shared__ float4 s_w2[RK * D4];
    __shared__ float4 s_b[D4], s_g[D4], s_lb[D4];
    __shared__ float4 s_x[16][D4 + 1];

    int tid = threadIdx.x;
    for (int i = tid; i < D * RK; i += 256) {
        int k = i >> 4, r = i & 15;
        ((float*)&s_w1t[r][k >> 2])[k & 3] = w1[i];
        ((float*)s_w2)[i] = w2[i];
    }
    if (tid < D) {
        ((float*)s_b)[tid]  = bias[tid];
        ((float*)s_g)[tid]  = lng[tid];
        ((float*)s_lb)[tid] = lnb[tid];
    }
    __syncthreads();

    int row = tid >> 4, lane = tid & 15;
    size_t lim = (size_t)N * D4;

    for (int c = blockIdx.x; c < nChunks; c += gridDim.x) {
        int n = c * 16 + row;
        __syncwarp();
        {
            size_t idx = (size_t)c * 256 + tid;
            s_x[row][lane] = ((const float4*)nf)[idx < lim ? idx : lim - 1];
        }

        // early gather of segment sums (latency overlap with compute)
        int n_cl = n < N ? n : N - 1;
        size_t o = (size_t)n_cl * D4 + lane;
        ulonglong2 hn = *(const ulonglong2*)&g_Sh[o];
        ulonglong2 hd = *(const ulonglong2*)&g_Ss[o];

        __syncwarp();

        ull p = 0;
#pragma unroll
        for (int k4 = 0; k4 < D4; k4++) {
            ulonglong2 xv = *(const ulonglong2*)&s_x[row][k4];
            ulonglong2 wv = *(const ulonglong2*)&s_w1t[lane][k4];
            p = fma2(xv.x, wv.x, p);
            p = fma2(xv.y, wv.y, p);
        }
        float t; { float a, b; upk2(p, a, b); t = a + b; }

        ulonglong2 bb = *(const ulonglong2*)&s_b[lane];
        ull acc0 = bb.x, acc1 = bb.y;
#pragma unroll
        for (int r = 0; r < RK; r++) {
            float u = __shfl_sync(0xffffffffu, t, r, 16);
            ull up = pk2(u, u);
            ulonglong2 w = *(const ulonglong2*)&s_w2[r * D4 + lane];
            acc0 = fma2(up, w.x, acc0);
            acc1 = fma2(up, w.y, acc1);
        }

        float m0, m1, m2, m3, q0, q1, q2, q3, d0, d1, d2, d3;
        upk2(acc0, m0, m1); upk2(acc1, m2, m3);
        upk2(hn.x, q0, q1); upk2(hn.y, q2, q3);
        upk2(hd.x, d0, d1); upk2(hd.y, d2, d3);
        m0 += q0 * __fdividef(1.f, d0 + 1e-6f);
        m1 += q1 * __fdividef(1.f, d1 + 1e-6f);
        m2 += q2 * __fdividef(1.f, d2 + 1e-6f);
        m3 += q3 * __fdividef(1.f, d3 + 1e-6f);

        float sum = m0 + m1 + m2 + m3;
        float ssq = m0*m0 + m1*m1 + m2*m2 + m3*m3;
#pragma unroll
        for (int off = 8; off; off >>= 1) {
            sum += __shfl_xor_sync(0xffffffffu, sum, off);
            ssq += __shfl_xor_sync(0xffffffffu, ssq, off);
        }
        float mu = sum * (1.0f / D);
        float rstd = rsqrtf(fmaf(-mu, mu, ssq * (1.0f / D)) + 1e-5f);

        float4 gg = s_g[lane], lb = s_lb[lane], xn = s_x[row][lane];
        float v0 = (m0 - mu) * rstd * gg.x + lb.x;
        float v1 = (m1 - mu) * rstd * gg.y + lb.y;
        float v2 = (m2 - mu) * rstd * gg.z + lb.z;
        float v3 = (m3 - mu) * rstd * gg.w + lb.w;
        float4 ov = make_float4(v0 * sigm(v0) + xn.x, v1 * sigm(v1) + xn.y,
                                v2 * sigm(v2) + xn.z, v3 * sigm(v3) + xn.w);
        if (n < N) ((float4*)xout)[(size_t)n * D4 + lane] = ov;
    }
}

// ---------------------------------------------------------------------- launch
extern "C" void kernel_launch(void* const* d_in, const int* in_sizes, int n_in,
                              void* d_out, int out_size)
{
    const float* nf  = (const float*)d_in[0];
    const float* ef  = (const float*)d_in[1];
    const int*   src = (const int*)d_in[2];
    const int*   dst = (const int*)d_in[3];
    const float* sgw1 = (const float*)d_in[4];
    const float* sgw2 = (const float*)d_in[5];
    const float* sgb  = (const float*)d_in[6];
    const float* dgw1 = (const float*)d_in[7];
    const float* dgw2 = (const float*)d_in[8];
    const float* dgb  = (const float*)d_in[9];
    const float* egw1 = (const float*)d_in[10];
    const float* egw2 = (const float*)d_in[11];
    const float* egb  = (const float*)d_in[12];
    const float* suw1 = (const float*)d_in[13];
    const float* suw2 = (const float*)d_in[14];
    const float* sub  = (const float*)d_in[15];
    const float* duw1 = (const float*)d_in[16];
    const float* duw2 = (const float*)d_in[17];
    const float* dub  = (const float*)d_in[18];
    const float* ln_n_g = (const float*)d_in[19];
    const float* ln_n_b = (const float*)d_in[20];
    const float* ln_e_g = (const float*)d_in[21];
    const float* ln_e_b = (const float*)d_in[22];

    int N = in_sizes[0] / D;
    int E = in_sizes[2];

    float* xout = (float*)d_out;
    float* yout = xout + (size_t)N * D;

    int ncN = (N + 15) / 16;
    int ncE = (E + 31) / 32;

    int gN = ncN < NBLK ? ncN : NBLK;
    int gE = ncE < NBLK ? ncE : NBLK;

    k_nodepre<<<gN, 256>>>(nf, N, ncN,
                           sgw1, sgw2, sgb,
                           dgw1, dgw2, dgb,
                           duw1, duw2, dub);
    k_edge<<<gE, 256>>>(ef, src, dst,
                        egw1, egw2, egb,
                        ln_e_g, ln_e_b, yout, E, ncE);
    k_nodeupd<<<gN, 256>>>(nf, suw1, suw2, sub,
                           ln_n_g, ln_n_b, xout, N, ncN);
}

// round 5
// speedup vs baseline: 3.9533x; 1.1678x over previous
#include <cuda_runtime.h>

#define D    64
#define D4   16
#define RK   16
#define MAXN 100000
#define NBLK 592

typedef unsigned long long ull;

// Scratch (allocation-free rule: __device__ globals). float4 for 16B alignment.
static __device__ float4 g_Asrc[(size_t)MAXN * D4];
static __device__ float4 g_Adst[(size_t)MAXN * D4];
static __device__ float4 g_Abh [(size_t)MAXN * D4];
static __device__ float4 g_Sh  [(size_t)MAXN * D4];
static __device__ float4 g_Ss  [(size_t)MAXN * D4];

// sigmoid via HW tanh: sigmoid(x) = 0.5*tanh(0.5x) + 0.5   (1 MUFU instead of 2)
__device__ __forceinline__ float sigm(float x) {
    float t;
    asm("tanh.approx.f32 %0, %1;" : "=f"(t) : "f"(0.5f * x));
    return fmaf(0.5f, t, 0.5f);
}
__device__ __forceinline__ void red_add_v4(float4* p, float4 v) {
    asm volatile("red.global.add.v4.f32 [%0], {%1,%2,%3,%4};"
                 :: "l"(p), "f"(v.x), "f"(v.y), "f"(v.z), "f"(v.w) : "memory");
}
// packed fp32x2 helpers (sm_100+)
__device__ __forceinline__ ull pk2(float lo, float hi) {
    ull r; asm("mov.b64 %0,{%1,%2};" : "=l"(r) : "f"(lo), "f"(hi)); return r;
}
__device__ __forceinline__ void upk2(ull v, float& lo, float& hi) {
    asm("mov.b64 {%0,%1},%2;" : "=f"(lo), "=f"(hi) : "l"(v));
}
__device__ __forceinline__ ull fma2(ull a, ull b, ull c) {
    ull d; asm("fma.rn.f32x2 %0,%1,%2,%3;" : "=l"(d) : "l"(a), "l"(b), "l"(c)); return d;
}
__device__ __forceinline__ ull add2(ull a, ull b) {
    ull d; asm("add.rn.f32x2 %0,%1,%2;" : "=l"(d) : "l"(a), "l"(b)); return d;
}

// ------------------------------------------------- node precompute (3 gates)
__global__ void __launch_bounds__(256) k_nodepre(
    const float* __restrict__ nf, int N, int nChunks,
    const float* __restrict__ w1a, const float* __restrict__ w2a, const float* __restrict__ ba,
    const float* __restrict__ w1b, const float* __restrict__ w2b, const float* __restrict__ bb,
    const float* __restrict__ w1c, const float* __restrict__ w2c, const float* __restrict__ bc)
{
    __shared__ float4 s_w1t[3][RK][D4 + 1];
    __shared__ float4 s_w2[3][RK * D4];
    __shared__ float4 s_b[3][D4];
    __shared__ float4 s_x[64][D4 + 1];

    int tid = threadIdx.x;
    for (int i = tid; i < D * RK; i += 256) {
        int k = i >> 4, r = i & 15;
        ((float*)&s_w1t[0][r][k >> 2])[k & 3] = w1a[i];
        ((float*)&s_w1t[1][r][k >> 2])[k & 3] = w1b[i];
        ((float*)&s_w1t[2][r][k >> 2])[k & 3] = w1c[i];
        ((float*)s_w2[0])[i] = w2a[i];
        ((float*)s_w2[1])[i] = w2b[i];
        ((float*)s_w2[2])[i] = w2c[i];
    }
    if (tid < D) {
        ((float*)s_b[0])[tid] = ba[tid];
        ((float*)s_b[1])[tid] = bb[tid];
        ((float*)s_b[2])[tid] = bc[tid];
    }
    __syncthreads();

    int row = tid >> 4, lane = tid & 15;
    size_t lim = (size_t)N * D4;
    float4 z = make_float4(0.f, 0.f, 0.f, 0.f);

    for (int c = blockIdx.x; c < nChunks; c += gridDim.x) {
        size_t base = (size_t)c * 1024 + tid;
        __syncwarp();
#pragma unroll
        for (int j = 0; j < 4; j++) {
            size_t idx = base + 256 * j;
            if (idx < lim) { g_Sh[idx] = z; g_Ss[idx] = z; }
            s_x[row + 16 * j][lane] = ((const float4*)nf)[idx < lim ? idx : lim - 1];
        }
        __syncwarp();

#pragma unroll
        for (int g = 0; g < 3; g++) {
            ull p0 = 0, p1 = 0, p2 = 0, p3 = 0;
#pragma unroll
            for (int k4 = 0; k4 < D4; k4++) {
                ulonglong2 w = *(const ulonglong2*)&s_w1t[g][lane][k4];
                ulonglong2 x0 = *(const ulonglong2*)&s_x[row][k4];
                ulonglong2 x1 = *(const ulonglong2*)&s_x[row + 16][k4];
                ulonglong2 x2 = *(const ulonglong2*)&s_x[row + 32][k4];
                ulonglong2 x3 = *(const ulonglong2*)&s_x[row + 48][k4];
                p0 = fma2(x0.x, w.x, p0); p0 = fma2(x0.y, w.y, p0);
                p1 = fma2(x1.x, w.x, p1); p1 = fma2(x1.y, w.y, p1);
                p2 = fma2(x2.x, w.x, p2); p2 = fma2(x2.y, w.y, p2);
                p3 = fma2(x3.x, w.x, p3); p3 = fma2(x3.y, w.y, p3);
            }
            float t0, t1, t2, t3;
            { float a, b;
              upk2(p0, a, b); t0 = a + b; upk2(p1, a, b); t1 = a + b;
              upk2(p2, a, b); t2 = a + b; upk2(p3, a, b); t3 = a + b; }

            ulonglong2 bb2 = *(const ulonglong2*)&s_b[g][lane];
            ull a00 = bb2.x, a01 = bb2.y, a10 = bb2.x, a11 = bb2.y;
            ull a20 = bb2.x, a21 = bb2.y, a30 = bb2.x, a31 = bb2.y;
#pragma unroll
            for (int r = 0; r < RK; r++) {
                ulonglong2 w = *(const ulonglong2*)&s_w2[g][r * D4 + lane];
                float u0 = __shfl_sync(0xffffffffu, t0, r, 16);
                float u1 = __shfl_sync(0xffffffffu, t1, r, 16);
                float u2 = __shfl_sync(0xffffffffu, t2, r, 16);
                float u3 = __shfl_sync(0xffffffffu, t3, r, 16);
                ull u0p = pk2(u0, u0), u1p = pk2(u1, u1);
                ull u2p = pk2(u2, u2), u3p = pk2(u3, u3);
                a00 = fma2(u0p, w.x, a00); a01 = fma2(u0p, w.y, a01);
                a10 = fma2(u1p, w.x, a10); a11 = fma2(u1p, w.y, a11);
                a20 = fma2(u2p, w.x, a20); a21 = fma2(u2p, w.y, a21);
                a30 = fma2(u3p, w.x, a30); a31 = fma2(u3p, w.y, a31);
            }
            float4* out = (g == 0) ? g_Asrc : (g == 1) ? g_Adst : g_Abh;
#pragma unroll
            for (int j = 0; j < 4; j++) {
                int n = c * 64 + row + 16 * j;
                if (n < N) {
                    ull lo = (j == 0) ? a00 : (j == 1) ? a10 : (j == 2) ? a20 : a30;
                    ull hi = (j == 0) ? a01 : (j == 1) ? a11 : (j == 2) ? a21 : a31;
                    *(ulonglong2*)&out[(size_t)n * D4 + lane] = make_ulonglong2(lo, hi);
                }
            }
        }
    }
}

// ------------------------------------------------------------------ edge pass
__global__ void __launch_bounds__(256) k_edge(
    const float* __restrict__ ef, const int* __restrict__ src, const int* __restrict__ dst,
    const float* __restrict__ w1, const float* __restrict__ w2, const float* __restrict__ bias,
    const float* __restrict__ lng, const float* __restrict__ lnb,
    float* __restrict__ yout, int E, int nChunks)
{
    __shared__ float4 s_w1t[RK][D4 + 1];
    __shared__ float4 s_w2[RK * D4];
    __shared__ float4 s_b[D4], s_g[D4], s_lb[D4];
    __shared__ float4 s_x[64][D4 + 1];

    int tid = threadIdx.x;
    for (int i = tid; i < D * RK; i += 256) {
        int k = i >> 4, r = i & 15;
        ((float*)&s_w1t[r][k >> 2])[k & 3] = w1[i];
        ((float*)s_w2)[i] = w2[i];
    }
    if (tid < D) {
        ((float*)s_b)[tid]  = bias[tid];
        ((float*)s_g)[tid]  = lng[tid];
        ((float*)s_lb)[tid] = lnb[tid];
    }
    __syncthreads();

    int row = tid >> 4, lane = tid & 15;
    size_t limE = (size_t)E;
    size_t lim4 = limE * D4;

    for (int c = blockIdx.x; c < nChunks; c += gridDim.x) {
        size_t e0 = (size_t)c * 64;
        size_t base = e0 * D4 + tid;

        __syncwarp();
#pragma unroll
        for (int j = 0; j < 4; j++) {
            size_t idx = base + 256 * j;
            s_x[row + 16 * j][lane] = ((const float4*)ef)[idx < lim4 ? idx : lim4 - 1];
        }

        int sj[4], dj[4];
#pragma unroll
        for (int j = 0; j < 4; j++) {
            size_t e = e0 + row + 16 * j;
            size_t ec = e < limE ? e : limE - 1;
            sj[j] = src[ec]; dj[j] = dst[ec];
        }
        ulonglong2 gs[4], gd[4];
#pragma unroll
        for (int j = 0; j < 4; j++) {
            gs[j] = *(const ulonglong2*)&g_Asrc[(size_t)sj[j] * D4 + lane];
            gd[j] = *(const ulonglong2*)&g_Adst[(size_t)dj[j] * D4 + lane];
        }

        __syncwarp();

        ull p0 = 0, p1 = 0, p2 = 0, p3 = 0;
#pragma unroll
        for (int k4 = 0; k4 < D4; k4++) {
            ulonglong2 w = *(const ulonglong2*)&s_w1t[lane][k4];
            ulonglong2 x0 = *(const ulonglong2*)&s_x[row][k4];
            ulonglong2 x1 = *(const ulonglong2*)&s_x[row + 16][k4];
            ulonglong2 x2 = *(const ulonglong2*)&s_x[row + 32][k4];
            ulonglong2 x3 = *(const ulonglong2*)&s_x[row + 48][k4];
            p0 = fma2(x0.x, w.x, p0); p0 = fma2(x0.y, w.y, p0);
            p1 = fma2(x1.x, w.x, p1); p1 = fma2(x1.y, w.y, p1);
            p2 = fma2(x2.x, w.x, p2); p2 = fma2(x2.y, w.y, p2);
            p3 = fma2(x3.x, w.x, p3); p3 = fma2(x3.y, w.y, p3);
        }
        float t0, t1, t2, t3;
        { float a, b;
          upk2(p0, a, b); t0 = a + b; upk2(p1, a, b); t1 = a + b;
          upk2(p2, a, b); t2 = a + b; upk2(p3, a, b); t3 = a + b; }

        ulonglong2 gh[4];
#pragma unroll
        for (int j = 0; j < 4; j++)
            gh[j] = *(const ulonglong2*)&g_Abh[(size_t)sj[j] * D4 + lane];

        ulonglong2 bb2 = *(const ulonglong2*)&s_b[lane];
        ull a00 = bb2.x, a01 = bb2.y, a10 = bb2.x, a11 = bb2.y;
        ull a20 = bb2.x, a21 = bb2.y, a30 = bb2.x, a31 = bb2.y;
#pragma unroll
        for (int r = 0; r < RK; r++) {
            ulonglong2 w = *(const ulonglong2*)&s_w2[r * D4 + lane];
            float u0 = __shfl_sync(0xffffffffu, t0, r, 16);
            float u1 = __shfl_sync(0xffffffffu, t1, r, 16);
            float u2 = __shfl_sync(0xffffffffu, t2, r, 16);
            float u3 = __shfl_sync(0xffffffffu, t3, r, 16);
            ull u0p = pk2(u0, u0), u1p = pk2(u1, u1);
            ull u2p = pk2(u2, u2), u3p = pk2(u3, u3);
            a00 = fma2(u0p, w.x, a00); a01 = fma2(u0p, w.y, a01);
            a10 = fma2(u1p, w.x, a10); a11 = fma2(u1p, w.y, a11);
            a20 = fma2(u2p, w.x, a20); a21 = fma2(u2p, w.y, a21);
            a30 = fma2(u3p, w.x, a30); a31 = fma2(u3p, w.y, a31);
        }

        float4 gg = s_g[lane], lb = s_lb[lane];

#pragma unroll
        for (int j = 0; j < 4; j++) {
            ull acc0 = (j == 0) ? a00 : (j == 1) ? a10 : (j == 2) ? a20 : a30;
            ull acc1 = (j == 0) ? a01 : (j == 1) ? a11 : (j == 2) ? a21 : a31;
            acc0 = add2(acc0, add2(gs[j].x, gd[j].x));
            acc1 = add2(acc1, add2(gs[j].y, gd[j].y));

            float m0, m1, m2, m3;
            upk2(acc0, m0, m1); upk2(acc1, m2, m3);

            float g0 = sigm(m0), g1 = sigm(m1), g2 = sigm(m2), g3 = sigm(m3);

            size_t e = e0 + row + 16 * j;
            bool valid = e < limE;
            size_t doff = (size_t)dj[j] * D4 + lane;
            if (valid) {
                float h0, h1, h2, h3;
                upk2(gh[j].x, h0, h1); upk2(gh[j].y, h2, h3);
                red_add_v4(&g_Ss[doff], make_float4(g0, g1, g2, g3));
                red_add_v4(&g_Sh[doff], make_float4(h0 * g0, h1 * g1, h2 * g2, h3 * g3));
            }

            float sum = m0 + m1 + m2 + m3;
            float ssq = m0*m0 + m1*m1 + m2*m2 + m3*m3;
#pragma unroll
            for (int off = 8; off; off >>= 1) {
                sum += __shfl_xor_sync(0xffffffffu, sum, off);
                ssq += __shfl_xor_sync(0xffffffffu, ssq, off);
            }
            float mu = sum * (1.0f / D);
            float rstd = rsqrtf(fmaf(-mu, mu, ssq * (1.0f / D)) + 1e-5f);

            float4 xe = s_x[row + 16 * j][lane];
            float v0 = (m0 - mu) * rstd * gg.x + lb.x;
            float v1 = (m1 - mu) * rstd * gg.y + lb.y;
            float v2 = (m2 - mu) * rstd * gg.z + lb.z;
            float v3 = (m3 - mu) * rstd * gg.w + lb.w;
            float4 o = make_float4(v0 * sigm(v0) + xe.x, v1 * sigm(v1) + xe.y,
                                   v2 * sigm(v2) + xe.z, v3 * sigm(v3) + xe.w);
            if (valid) ((float4*)yout)[e * D4 + lane] = o;
        }
    }
}

// ------------------------------------------------------------- node update
__global__ void __launch_bounds__(256) k_nodeupd(
    const float* __restrict__ nf,
    const float* __restrict__ w1, const float* __restrict__ w2, const float* __restrict__ bias,
    const float* __restrict__ lng, const float* __restrict__ lnb,
    float* __restrict__ xout, int N, int nChunks)
{
    __shared__ float4 s_w1t[RK][D4 + 1];
    __shared__ float4 s_w2[RK * D4];
    __shared__ float4 s_b[D4], s_g[D4], s_lb[D4];
    __shared__ float4 s_x[64][D4 + 1];

    int tid = threadIdx.x;
    for (int i = tid; i < D * RK; i += 256) {
        int k = i >> 4, r = i & 15;
        ((float*)&s_w1t[r][k >> 2])[k & 3] = w1[i];
        ((float*)s_w2)[i] = w2[i];
    }
    if (tid < D) {
        ((float*)s_b)[tid]  = bias[tid];
        ((float*)s_g)[tid]  = lng[tid];
        ((float*)s_lb)[tid] = lnb[tid];
    }
    __syncthreads();

    int row = tid >> 4, lane = tid & 15;
    size_t lim = (size_t)N * D4;

    for (int c = blockIdx.x; c < nChunks; c += gridDim.x) {
        size_t base = (size_t)c * 1024 + tid;
        __syncwarp();
#pragma unroll
        for (int j = 0; j < 4; j++) {
            size_t idx = base + 256 * j;
            s_x[row + 16 * j][lane] = ((const float4*)nf)[idx < lim ? idx : lim - 1];
        }

        ulonglong2 hn[4], hd[4];
#pragma unroll
        for (int j = 0; j < 4; j++) {
            int n = c * 64 + row + 16 * j;
            int n_cl = n < N ? n : N - 1;
            size_t o = (size_t)n_cl * D4 + lane;
            hn[j] = *(const ulonglong2*)&g_Sh[o];
            hd[j] = *(const ulonglong2*)&g_Ss[o];
        }

        __syncwarp();

        ull p0 = 0, p1 = 0, p2 = 0, p3 = 0;
#pragma unroll
        for (int k4 = 0; k4 < D4; k4++) {
            ulonglong2 w = *(const ulonglong2*)&s_w1t[lane][k4];
            ulonglong2 x0 = *(const ulonglong2*)&s_x[row][k4];
            ulonglong2 x1 = *(const ulonglong2*)&s_x[row + 16][k4];
            ulonglong2 x2 = *(const ulonglong2*)&s_x[row + 32][k4];
            ulonglong2 x3 = *(const ulonglong2*)&s_x[row + 48][k4];
            p0 = fma2(x0.x, w.x, p0); p0 = fma2(x0.y, w.y, p0);
            p1 = fma2(x1.x, w.x, p1); p1 = fma2(x1.y, w.y, p1);
            p2 = fma2(x2.x, w.x, p2); p2 = fma2(x2.y, w.y, p2);
            p3 = fma2(x3.x, w.x, p3); p3 = fma2(x3.y, w.y, p3);
        }
        float t0, t1, t2, t3;
        { float a, b;
          upk2(p0, a, b); t0 = a + b; upk2(p1, a, b); t1 = a + b;
          upk2(p2, a, b); t2 = a + b; upk2(p3, a, b); t3 = a + b; }

        ulonglong2 bb2 = *(const ulonglong2*)&s_b[lane];
        ull a00 = bb2.x, a01 = bb2.y, a10 = bb2.x, a11 = bb2.y;
        ull a20 = bb2.x, a21 = bb2.y, a30 = bb2.x, a31 = bb2.y;
#pragma unroll
        for (int r = 0; r < RK; r++) {
            ulonglong2 w = *(const ulonglong2*)&s_w2[r * D4 + lane];
            float u0 = __shfl_sync(0xffffffffu, t0, r, 16);
            float u1 = __shfl_sync(0xffffffffu, t1, r, 16);
            float u2 = __shfl_sync(0xffffffffu, t2, r, 16);
            float u3 = __shfl_sync(0xffffffffu, t3, r, 16);
            ull u0p = pk2(u0, u0), u1p = pk2(u1, u1);
            ull u2p = pk2(u2, u2), u3p = pk2(u3, u3);
            a00 = fma2(u0p, w.x, a00); a01 = fma2(u0p, w.y, a01);
            a10 = fma2(u1p, w.x, a10); a11 = fma2(u1p, w.y, a11);
            a20 = fma2(u2p, w.x, a20); a21 = fma2(u2p, w.y, a21);
            a30 = fma2(u3p, w.x, a30); a31 = fma2(u3p, w.y, a31);
        }

        float4 gg = s_g[lane], lb = s_lb[lane];

#pragma unroll
        for (int j = 0; j < 4; j++) {
            ull acc0 = (j == 0) ? a00 : (j == 1) ? a10 : (j == 2) ? a20 : a30;
            ull acc1 = (j == 0) ? a01 : (j == 1) ? a11 : (j == 2) ? a21 : a31;
            float m0, m1, m2, m3, q0, q1, q2, q3, d0, d1, d2, d3;
            upk2(acc0, m0, m1); upk2(acc1, m2, m3);
            upk2(hn[j].x, q0, q1); upk2(hn[j].y, q2, q3);
            upk2(hd[j].x, d0, d1); upk2(hd[j].y, d2, d3);
            m0 += q0 * __fdividef(1.f, d0 + 1e-6f);
            m1 += q1 * __fdividef(1.f, d1 + 1e-6f);
            m2 += q2 * __fdividef(1.f, d2 + 1e-6f);
            m3 += q3 * __fdividef(1.f, d3 + 1e-6f);

            float sum = m0 + m1 + m2 + m3;
            float ssq = m0*m0 + m1*m1 + m2*m2 + m3*m3;
#pragma unroll
            for (int off = 8; off; off >>= 1) {
                sum += __shfl_xor_sync(0xffffffffu, sum, off);
                ssq += __shfl_xor_sync(0xffffffffu, ssq, off);
            }
            float mu = sum * (1.0f / D);
            float rstd = rsqrtf(fmaf(-mu, mu, ssq * (1.0f / D)) + 1e-5f);

            int n = c * 64 + row + 16 * j;
            float4 xn = s_x[row + 16 * j][lane];
            float v0 = (m0 - mu) * rstd * gg.x + lb.x;
            float v1 = (m1 - mu) * rstd * gg.y + lb.y;
            float v2 = (m2 - mu) * rstd * gg.z + lb.z;
            float v3 = (m3 - mu) * rstd * gg.w + lb.w;
            float4 ov = make_float4(v0 * sigm(v0) + xn.x, v1 * sigm(v1) + xn.y,
                                    v2 * sigm(v2) + xn.z, v3 * sigm(v3) + xn.w);
            if (n < N) ((float4*)xout)[(size_t)n * D4 + lane] = ov;
        }
    }
}

// ---------------------------------------------------------------------- launch
extern "C" void kernel_launch(void* const* d_in, const int* in_sizes, int n_in,
                              void* d_out, int out_size)
{
    const float* nf  = (const float*)d_in[0];
    const float* ef  = (const float*)d_in[1];
    const int*   src = (const int*)d_in[2];
    const int*   dst = (const int*)d_in[3];
    const float* sgw1 = (const float*)d_in[4];
    const float* sgw2 = (const float*)d_in[5];
    const float* sgb  = (const float*)d_in[6];
    const float* dgw1 = (const float*)d_in[7];
    const float* dgw2 = (const float*)d_in[8];
    const float* dgb  = (const float*)d_in[9];
    const float* egw1 = (const float*)d_in[10];
    const float* egw2 = (const float*)d_in[11];
    const float* egb  = (const float*)d_in[12];
    const float* suw1 = (const float*)d_in[13];
    const float* suw2 = (const float*)d_in[14];
    const float* sub  = (const float*)d_in[15];
    const float* duw1 = (const float*)d_in[16];
    const float* duw2 = (const float*)d_in[17];
    const float* dub  = (const float*)d_in[18];
    const float* ln_n_g = (const float*)d_in[19];
    const float* ln_n_b = (const float*)d_in[20];
    const float* ln_e_g = (const float*)d_in[21];
    const float* ln_e_b = (const float*)d_in[22];

    int N = in_sizes[0] / D;
    int E = in_sizes[2];

    float* xout = (float*)d_out;
    float* yout = xout + (size_t)N * D;

    int ncN = (N + 63) / 64;
    int ncE = (E + 63) / 64;

    int gN = ncN < NBLK ? ncN : NBLK;
    int gE = ncE < NBLK ? ncE : NBLK;

    k_nodepre<<<gN, 256>>>(nf, N, ncN,
                           sgw1, sgw2, sgb,
                           dgw1, dgw2, dgb,
                           duw1, duw2, dub);
    k_edge<<<gE, 256>>>(ef, src, dst,
                        egw1, egw2, egb,
                        ln_e_g, ln_e_b, yout, E, ncE);
    k_nodeupd<<<gN, 256>>>(nf, suw1, suw2, sub,
                           ln_n_g, ln_n_b, xout, N, ncN);
}